// round 14
// baseline (speedup 1.0000x reference)
#include <cuda_runtime.h>
#include <cuda_bf16.h>
#include <cstdint>

#define B_ 4
#define T_ 1024
#define D_ 256
#define V_ 32000

// Scratch (allocation-free: device globals)
__device__ float g_E0[B_ * T_ * D_];   // E0[bt,d] = x_t @ Wx0^T + b0
__device__ float g_rnn[B_ * T_ * D_];  // h1(t) for all bt  (rnn_out)

// ---------------------------------------------------------------------------
// Kernel 1: E0[bt,d] = b0[d] + sum_{k<256} embed[ids[bt]][k] * W0[d][k]
// ---------------------------------------------------------------------------
__global__ void __launch_bounds__(256) e0_kernel(const int* __restrict__ ids,
                                                 const float* __restrict__ embed,
                                                 const float* __restrict__ W0,
                                                 const float* __restrict__ b0) {
    __shared__ float Xs[64][65];
    __shared__ float Ws[64][65];
    int tid = threadIdx.x;
    int bm = blockIdx.x * 64;
    int rq = tid >> 4, cq = tid & 15;
    int r0 = rq * 4, c0 = cq * 4;

    for (int dc = 0; dc < 256; dc += 64) {
        float acc[4][4];
#pragma unroll
        for (int i = 0; i < 4; i++)
#pragma unroll
            for (int j = 0; j < 4; j++) acc[i][j] = 0.f;

        for (int kc = 0; kc < 256; kc += 64) {
#pragma unroll
            for (int i = 0; i < 4; i++) {
                int e = tid + i * 256;
                int row = e >> 4;
                int c4 = e & 15;
                int id = ids[bm + row];
                float4 vx = *reinterpret_cast<const float4*>(
                    &embed[(size_t)id * 256 + kc + c4 * 4]);
                Xs[row][c4 * 4 + 0] = vx.x; Xs[row][c4 * 4 + 1] = vx.y;
                Xs[row][c4 * 4 + 2] = vx.z; Xs[row][c4 * 4 + 3] = vx.w;
                float4 vw = *reinterpret_cast<const float4*>(
                    &W0[(size_t)(dc + row) * 512 + kc + c4 * 4]);
                Ws[row][c4 * 4 + 0] = vw.x; Ws[row][c4 * 4 + 1] = vw.y;
                Ws[row][c4 * 4 + 2] = vw.z; Ws[row][c4 * 4 + 3] = vw.w;
            }
            __syncthreads();
#pragma unroll 8
            for (int k = 0; k < 64; k++) {
                float xa[4], wb[4];
#pragma unroll
                for (int i = 0; i < 4; i++) xa[i] = Xs[r0 + i][k];
#pragma unroll
                for (int j = 0; j < 4; j++) wb[j] = Ws[c0 + j][k];
#pragma unroll
                for (int i = 0; i < 4; i++)
#pragma unroll
                    for (int j = 0; j < 4; j++)
                        acc[i][j] = fmaf(xa[i], wb[j], acc[i][j]);
            }
            __syncthreads();
        }
#pragma unroll
        for (int i = 0; i < 4; i++)
#pragma unroll
            for (int j = 0; j < 4; j++)
                g_E0[(size_t)(bm + r0 + i) * 256 + dc + c0 + j] =
                    acc[i][j] + b0[dc + c0 + j];
    }
}

// ---------------------------------------------------------------------------
// Kernel 2: recurrence. 4 clusters (one per batch) x 8 CTAs x 512 threads.
// Iter t computes h0(t) (threads 0..255) and h1(t-1) (threads 256..511).
// Recurrent weights in registers; activations broadcast via DSMEM stores.
// ---------------------------------------------------------------------------
__device__ __forceinline__ void cluster_sync_() {
    asm volatile(
        "barrier.cluster.arrive.aligned;\n\t"
        "barrier.cluster.wait.aligned;" ::: "memory");
}

__device__ __forceinline__ void bcast2(float* addr, float v0, float v1) {
    uint32_t la = (uint32_t)__cvta_generic_to_shared(addr);
    unsigned long long bits;
    asm("mov.b64 %0, {%1,%2};" : "=l"(bits) : "f"(v0), "f"(v1));
#pragma unroll
    for (int r = 0; r < 8; r++) {
        uint32_t ra;
        asm("mapa.shared::cluster.u32 %0, %1, %2;" : "=r"(ra) : "r"(la), "r"(r));
        asm volatile("st.shared::cluster.b64 [%0], %1;" ::"r"(ra), "l"(bits)
                     : "memory");
    }
}

__global__ void __cluster_dims__(8, 1, 1) __launch_bounds__(512)
rnn_kernel(const float* __restrict__ W0, const float* __restrict__ W1,
           const float* __restrict__ b1, float* __restrict__ hid_out) {
    __shared__ __align__(16) float h0buf[2][256];
    __shared__ __align__(16) float h1buf[2][256];
    int tid = threadIdx.x;
    unsigned rank;
    asm("mov.u32 %0, %%cluster_ctarank;" : "=r"(rank));
    int b = blockIdx.x >> 3;
    int c = (int)rank;

    for (int i = tid; i < 256; i += 512) {
        h0buf[0][i] = 0.f; h0buf[1][i] = 0.f;
        h1buf[0][i] = 0.f; h1buf[1][i] = 0.f;
    }

    bool is_h1 = (tid >= 256);
    int tt = is_h1 ? (tid - 256) : tid;
    int p = tt >> 4, g = tt & 15;     // 16 output-pair groups x 16 lanes
    int d0 = c * 32 + 2 * p;          // this group's two output dims

    // Register-resident recurrent weights; k = g + 16*i striding gives
    // conflict-free broadcast reads of the activation buffers.
    float wa[32], wb[32];
#pragma unroll
    for (int i = 0; i < 32; i++) { wa[i] = 0.f; wb[i] = 0.f; }
    if (!is_h1) {
#pragma unroll
        for (int i = 0; i < 16; i++) {
            wa[i] = W0[(size_t)d0 * 512 + 256 + g + 16 * i];
            wb[i] = W0[(size_t)(d0 + 1) * 512 + 256 + g + 16 * i];
        }
    } else {
#pragma unroll
        for (int i = 0; i < 16; i++) {
            wa[i] = W1[(size_t)d0 * 512 + g + 16 * i];             // h0 part
            wb[i] = W1[(size_t)(d0 + 1) * 512 + g + 16 * i];
            wa[16 + i] = W1[(size_t)d0 * 512 + 256 + g + 16 * i];  // h1 part
            wb[16 + i] = W1[(size_t)(d0 + 1) * 512 + 256 + g + 16 * i];
        }
    }
    float bias0 = 0.f, bias1 = 0.f;
    if (is_h1 && g == 0) { bias0 = b1[d0]; bias1 = b1[d0 + 1]; }

    cluster_sync_();  // peers' buffers zeroed before any remote store

#pragma unroll 1
    for (int t = 0; t <= T_; t++) {
        int rp = (t + 1) & 1;  // parity holding h0(t-1)
        float e0a = 0.f, e0b = 0.f;
        float acc0 = 0.f, acc1 = 0.f;
        if (!is_h1) {
            if (t < T_) {
                if (g == 0) {  // prefetch E0; consumed after reduction
                    e0a = g_E0[(size_t)(b * T_ + t) * 256 + d0];
                    e0b = g_E0[(size_t)(b * T_ + t) * 256 + d0 + 1];
                }
#pragma unroll
                for (int i = 0; i < 16; i++) {
                    float a = h0buf[rp][g + 16 * i];        // h0(t-1)
                    acc0 = fmaf(wa[i], a, acc0);
                    acc1 = fmaf(wb[i], a, acc1);
                }
            }
        } else {
            if (t >= 1) {
#pragma unroll
                for (int i = 0; i < 16; i++) {
                    float a = h0buf[rp][g + 16 * i];        // h0(t-1)
                    acc0 = fmaf(wa[i], a, acc0);
                    acc1 = fmaf(wb[i], a, acc1);
                }
#pragma unroll
                for (int i = 0; i < 16; i++) {
                    float a = h1buf[t & 1][g + 16 * i];     // h1(t-2)
                    acc0 = fmaf(wa[16 + i], a, acc0);
                    acc1 = fmaf(wb[16 + i], a, acc1);
                }
            }
        }
#pragma unroll
        for (int off = 8; off; off >>= 1) {
            acc0 += __shfl_down_sync(0xffffffffu, acc0, off, 16);
            acc1 += __shfl_down_sync(0xffffffffu, acc1, off, 16);
        }
        if (g == 0) {
            if (!is_h1) {
                if (t < T_) {
                    float v0 = tanhf(e0a + acc0);
                    float v1 = tanhf(e0b + acc1);
                    bcast2(&h0buf[t & 1][d0], v0, v1);
                }
            } else {
                if (t >= 1) {
                    float v0 = tanhf(acc0 + bias0);
                    float v1 = tanhf(acc1 + bias1);
                    bcast2(&h1buf[(t + 1) & 1][d0], v0, v1);
                    g_rnn[(size_t)(b * T_ + (t - 1)) * 256 + d0] = v0;
                    g_rnn[(size_t)(b * T_ + (t - 1)) * 256 + d0 + 1] = v1;
                }
            }
        }
        cluster_sync_();
    }

    // final_hidden (2, B, D): h0(T-1) parity (T-1)&1, h1(T-1) parity (T+1)&1
    if (hid_out != nullptr && rank == 0) {
        if (tid < 256)
            hid_out[(0 * B_ + b) * 256 + tid] = h0buf[(T_ - 1) & 1][tid];
        else
            hid_out[(1 * B_ + b) * 256 + (tid - 256)] =
                h1buf[(T_ + 1) & 1][tid - 256];
    }
}

// ---------------------------------------------------------------------------
// Kernel 3: logits = rnn_out @ head_w^T via mma.sync.m16n8k8 tf32.
// 256 threads, 128(bt) x 128(v) tile, K=256 in 32-wide chunks.
// ---------------------------------------------------------------------------
__device__ __forceinline__ float tf32r(float x) {
    uint32_t u;
    asm("cvt.rna.tf32.f32 %0, %1;" : "=r"(u) : "f"(x));
    return __uint_as_float(u);
}

__device__ __forceinline__ void mma_tf32(float* c, uint32_t a0, uint32_t a1,
                                         uint32_t a2, uint32_t a3, uint32_t b0,
                                         uint32_t b1) {
    asm volatile(
        "mma.sync.aligned.m16n8k8.row.col.f32.tf32.tf32.f32 "
        "{%0,%1,%2,%3}, {%4,%5,%6,%7}, {%8,%9}, {%0,%1,%2,%3};"
        : "+f"(c[0]), "+f"(c[1]), "+f"(c[2]), "+f"(c[3])
        : "r"(a0), "r"(a1), "r"(a2), "r"(a3), "r"(b0), "r"(b1));
}

__global__ void __launch_bounds__(256) head_kernel(const float* __restrict__ Wh,
                                                   float* __restrict__ out) {
    __shared__ float As[128][36];
    __shared__ float Bs[128][36];
    int tid = threadIdx.x;
    int bm = blockIdx.y * 128;   // bt tile
    int bn = blockIdx.x * 128;   // vocab tile
    int warp = tid >> 5, lane = tid & 31;
    int wm = (warp >> 2) * 64, wn = (warp & 3) * 32;
    int gid = lane >> 2, tig = lane & 3;

    float acc[4][4][4];
#pragma unroll
    for (int mt = 0; mt < 4; mt++)
#pragma unroll
        for (int nt = 0; nt < 4; nt++)
#pragma unroll
            for (int r = 0; r < 4; r++) acc[mt][nt][r] = 0.f;

    for (int kc = 0; kc < 256; kc += 32) {
#pragma unroll
        for (int i = 0; i < 4; i++) {
            int e = tid + i * 256;
            int row = e >> 3;
            int c4 = e & 7;
            float4 va = *reinterpret_cast<const float4*>(
                &g_rnn[(size_t)(bm + row) * 256 + kc + c4 * 4]);
            As[row][c4 * 4 + 0] = tf32r(va.x); As[row][c4 * 4 + 1] = tf32r(va.y);
            As[row][c4 * 4 + 2] = tf32r(va.z); As[row][c4 * 4 + 3] = tf32r(va.w);
            float4 vb = *reinterpret_cast<const float4*>(
                &Wh[(size_t)(bn + row) * 256 + kc + c4 * 4]);
            Bs[row][c4 * 4 + 0] = tf32r(vb.x); Bs[row][c4 * 4 + 1] = tf32r(vb.y);
            Bs[row][c4 * 4 + 2] = tf32r(vb.z); Bs[row][c4 * 4 + 3] = tf32r(vb.w);
        }
        __syncthreads();
#pragma unroll
        for (int ks = 0; ks < 32; ks += 8) {
            uint32_t bf[4][2];
#pragma unroll
            for (int nt = 0; nt < 4; nt++) {
                bf[nt][0] = __float_as_uint(Bs[wn + nt * 8 + gid][ks + tig]);
                bf[nt][1] = __float_as_uint(Bs[wn + nt * 8 + gid][ks + tig + 4]);
            }
#pragma unroll
            for (int mt = 0; mt < 4; mt++) {
                uint32_t a0 = __float_as_uint(As[wm + mt * 16 + gid][ks + tig]);
                uint32_t a1 = __float_as_uint(As[wm + mt * 16 + gid + 8][ks + tig]);
                uint32_t a2 = __float_as_uint(As[wm + mt * 16 + gid][ks + tig + 4]);
                uint32_t a3 = __float_as_uint(As[wm + mt * 16 + gid + 8][ks + tig + 4]);
#pragma unroll
                for (int nt = 0; nt < 4; nt++)
                    mma_tf32(acc[mt][nt], a0, a1, a2, a3, bf[nt][0], bf[nt][1]);
            }
        }
        __syncthreads();
    }

#pragma unroll
    for (int mt = 0; mt < 4; mt++)
#pragma unroll
        for (int nt = 0; nt < 4; nt++) {
            int row = bm + wm + mt * 16 + gid;
            int col = bn + wn + nt * 8 + 2 * tig;
            float2 v01 = make_float2(acc[mt][nt][0], acc[mt][nt][1]);
            float2 v23 = make_float2(acc[mt][nt][2], acc[mt][nt][3]);
            *reinterpret_cast<float2*>(&out[(size_t)row * V_ + col]) = v01;
            *reinterpret_cast<float2*>(&out[(size_t)(row + 8) * V_ + col]) = v23;
        }
}

// ---------------------------------------------------------------------------
extern "C" void kernel_launch(void* const* d_in, const int* in_sizes, int n_in,
                              void* d_out, int out_size) {
    const int* ids = (const int*)d_in[0];
    const float* embed = (const float*)d_in[1];
    const float* W0 = (const float*)d_in[2];
    const float* b0 = (const float*)d_in[3];
    const float* W1 = (const float*)d_in[4];
    const float* b1 = (const float*)d_in[5];
    const float* Wh = (const float*)d_in[6];
    float* out = (float*)d_out;

    // final_hidden lives after the logits iff the harness sized d_out for it.
    const size_t logits_elems = (size_t)B_ * T_ * V_;
    float* hid = nullptr;
    if ((size_t)out_size >= logits_elems + 2 * B_ * D_)
        hid = out + logits_elems;

    e0_kernel<<<(B_ * T_) / 64, 256>>>(ids, embed, W0, b0);
    rnn_kernel<<<B_ * 8, 512>>>(W0, W1, b1, hid);
    dim3 hg(V_ / 128, (B_ * T_) / 128);
    head_kernel<<<hg, 256>>>(Wh, out);
}